// round 14
// baseline (speedup 1.0000x reference)
#include <cuda_runtime.h>
#include <cuda_fp16.h>
#include <cstdint>

#define E_DIM 512
#define NH    8
#define HD    64
#define BB    8
#define NPAD  1025
#define NTOK  1024
#define MTOT  (BB * NPAD)   // 8200
#define MWORDS 34
#define VPITCH 1088         // 17*64: padded key count for transposed V (halves)

// softmax in log2 domain: exp(x) = exp2(x * LOG2E); fixed reference M2 = 16
#define LOG2E 1.44269504f
#define QSCALE (0.125f * LOG2E)
#define M2REF 16.0f

// K/V smem row stride 40 u32 (== 8 mod 32 -> conflict-free LDS.64 fragments)
#define KV_STRIDE 40
// stage (u32): Ks@0 [64][40], Vt@2560 [64][40], Bs@5120 [128][68] f32,
//              Mk@13824 [128][2]  -> 14080 u32 = 56320 B per stage, 2 stages
#define STAGE_U32 14080
#define STAGE_B   56320
#define QTILE 128

// fragment-pair permutation within a 64-half (32-u32) group:
// old fragment words {8kc+tig, 8kc+tig+4} -> adjacent {8kc+2tig, 8kc+2tig+1}
__host__ __device__ __forceinline__ int pperm(int p) {
    return ((p >> 3) << 3) + ((p & 3) << 1) + ((p >> 2) & 1);
}

// Scratch (allocation-free rule: __device__ globals)
__device__ __half   g_xh [MTOT * E_DIM];
__device__ __half   g_wh [4 * E_DIM * E_DIM];
__device__ __half   g_qh [BB * NH * NPAD * HD];       // q * 0.125*log2e
__device__ __half   g_kh [BB * NH * NPAD * HD];       // [b,h][row][d] (pair-permuted)
__device__ __half   g_vt [BB * NH * HD * VPITCH];     // [b,h][d][key] (pair-permuted per 64-key tile)
__device__ __half   g_atth[MTOT * E_DIM];             // [b,row][h*64+d]
__device__ uint32_t g_mbits[BB * NPAD * MWORDS];

// ---------------------------------------------------------------------------
__device__ __forceinline__ uint32_t f2h2(float lo, float hi) {
    uint32_t r;
    asm("cvt.rn.f16x2.f32 %0, %1, %2;" : "=r"(r) : "f"(hi), "f"(lo));
    return r;
}
__device__ __forceinline__ float ex2(float x) {
    float r;
    asm("ex2.approx.ftz.f32 %0, %1;" : "=f"(r) : "f"(x));
    return r;
}
__device__ __forceinline__ void mma16(float* c, const uint32_t* a, const uint32_t* b) {
    asm volatile(
        "mma.sync.aligned.m16n8k16.row.col.f32.f16.f16.f32 "
        "{%0,%1,%2,%3}, {%4,%5,%6,%7}, {%8,%9}, {%0,%1,%2,%3};\n"
        : "+f"(c[0]), "+f"(c[1]), "+f"(c[2]), "+f"(c[3])
        : "r"(a[0]), "r"(a[1]), "r"(a[2]), "r"(a[3]), "r"(b[0]), "r"(b[1]));
}
__device__ __forceinline__ uint32_t smem_u32(const void* p) {
    uint32_t a;
    asm("{.reg .u64 t; cvta.to.shared.u64 t, %1; cvt.u32.u64 %0, t;}" : "=r"(a) : "l"(p));
    return a;
}
__device__ __forceinline__ void cpa16(uint32_t dst, const void* src, bool ok) {
    asm volatile("cp.async.ca.shared.global [%0], [%1], 16, %2;"
                 :: "r"(dst), "l"(src), "r"(ok ? 16 : 0));
}
__device__ __forceinline__ void cpa8(uint32_t dst, const void* src, bool ok) {
    asm volatile("cp.async.ca.shared.global [%0], [%1], 8, %2;"
                 :: "r"(dst), "l"(src), "r"(ok ? 8 : 0));
}
#define CP_COMMIT() asm volatile("cp.async.commit_group;")
#define CP_WAIT1()  asm volatile("cp.async.wait_group 1;")
#define CP_WAIT0()  asm volatile("cp.async.wait_group 0;")

// ---------------------------------------------------------------------------
// Fused prep: x->half, W->half, g_vt pad zero, pack mask bits.
// ---------------------------------------------------------------------------
#define XCNT (MTOT * E_DIM)                 // 4,198,400
#define WCNT (4 * E_DIM * E_DIM)            // 1,048,576
#define PADCNT (BB * NH * HD * 63)          // 258,048
#define MASKCNT (BB * NPAD * MWORDS)        // 278,800
#define PREP_TOTAL (XCNT + WCNT + PADCNT + MASKCNT)
__global__ void prep_all(const float* __restrict__ x,
                         const float* __restrict__ Wq, const float* __restrict__ Wk,
                         const float* __restrict__ Wv, const float* __restrict__ Wo,
                         const int* __restrict__ pm)
{
    int idx = blockIdx.x * 256 + threadIdx.x;
    if (idx < XCNT) {
        g_xh[idx] = __float2half(x[idx]);
    } else if (idx < XCNT + WCNT) {
        int wi = idx - XCNT;
        int m = wi >> 18, off = wi & 262143;
        const float* W = (m == 0) ? Wq : (m == 1) ? Wk : (m == 2) ? Wv : Wo;
        g_wh[wi] = __float2half(W[off]);
    } else if (idx < XCNT + WCNT + PADCNT) {
        int e = idx - XCNT - WCNT;
        int p = e % 63, rest = e / 63;   // keys 1025..1087 (stored order)
        g_vt[(size_t)rest * VPITCH + NPAD + p] = __float2half(0.f);
    } else if (idx < PREP_TOTAL) {
        int mi = idx - XCNT - WCNT - PADCNT;
        int w = mi % MWORDS;
        int row = (mi / MWORDS) % NPAD;
        int b = mi / (MWORDS * NPAD);
        uint32_t bits = 0;
        for (int i = 0; i < 32; i++) {
            int col = w * 32 + i;
            if (col >= NPAD) break;
            bool keep;
            if (row == 0 || col == 0) keep = true;
            else keep = __ldg(&pm[(b * NTOK + row - 1) * NTOK + col - 1]) != 0;
            if (keep) bits |= (1u << i);
        }
        g_mbits[mi] = bits;
    }
}

// ---------------------------------------------------------------------------
// fp16 GEMM: C = A @ W^T + b.  128x128 CTA tile, K-chunk 64, 2-stage cp.async.
// qkv=1: mode = blockIdx.z (0:q scaled by 0.125*log2e, 1:k permuted,
//        2:v transposed+permuted). qkv=0: O-proj, fp32 out.
// ---------------------------------------------------------------------------
__global__ __launch_bounds__(256) void gemm_f16(
    const float* __restrict__ b0, const float* __restrict__ b1,
    const float* __restrict__ b2, float* __restrict__ outp, int qkv)
{
    extern __shared__ __align__(16) __half smg[];
    const uint32_t sb = smem_u32(smg);
    const uint32_t* smu = (const uint32_t*)smg;

    const int mode = qkv ? blockIdx.z : 3;
    const __half* A = qkv ? g_xh : g_atth;
    const __half* W = g_wh + (size_t)mode * E_DIM * E_DIM;
    const float* bias = (mode == 0) ? b0 : (mode == 1) ? b1 : (mode == 2) ? b2 : b0;

    const int tid = threadIdx.x;
    const int lane = tid & 31, warp = tid >> 5;
    const int g = lane >> 2, tig = lane & 3;
    const int wm = (warp & 3) * 32, wn = (warp >> 2) * 64;
    const int m0 = blockIdx.y * 128, n0 = blockIdx.x * 128;

    auto stage = [&](int buf, int kc) {
        const uint32_t abase = sb + buf * 18432;
        const uint32_t wbase = sb + 36864 + buf * 18432;
#pragma unroll
        for (int it = 0; it < 4; it++) {
            const int idx = it * 256 + tid;          // 0..1023
            const int row = idx >> 3, c = idx & 7;
            const int m = m0 + row;
            cpa16(abase + row * 144 + c * 16,
                  A + (size_t)m * E_DIM + kc + c * 8, m < MTOT);
        }
#pragma unroll
        for (int it = 0; it < 4; it++) {
            const int idx = it * 256 + tid;
            const int row = idx >> 3, c = idx & 7;
            cpa16(wbase + row * 144 + c * 16,
                  W + (size_t)(n0 + row) * E_DIM + kc + c * 8, true);
        }
    };

    float acc[2][8][4];
#pragma unroll
    for (int mt = 0; mt < 2; mt++)
#pragma unroll
        for (int nt = 0; nt < 8; nt++)
#pragma unroll
            for (int e = 0; e < 4; e++) acc[mt][nt][e] = 0.f;

    stage(0, 0); CP_COMMIT();

    for (int ch = 0; ch < 8; ch++) {
        if (ch < 7) { stage((ch + 1) & 1, (ch + 1) * 64); CP_COMMIT(); }
        if (ch < 7) CP_WAIT1(); else CP_WAIT0();
        __syncthreads();

        const uint32_t* Au = smu + ((ch & 1) ? 4608 : 0);
        const uint32_t* Wu = smu + 9216 + ((ch & 1) ? 4608 : 0);
#pragma unroll
        for (int ks = 0; ks < 4; ks++) {
            uint32_t a[2][4];
#pragma unroll
            for (int mt = 0; mt < 2; mt++) {
                const int r = wm + 16 * mt + g;
                const uint32_t* p = Au + r * 36 + ks * 8 + tig;
                a[mt][0] = p[0];
                a[mt][1] = p[8 * 36];
                a[mt][2] = p[4];
                a[mt][3] = p[8 * 36 + 4];
            }
            uint32_t bf[8][2];
#pragma unroll
            for (int nt = 0; nt < 8; nt++) {
                const uint32_t* p = Wu + (wn + 8 * nt + g) * 36 + ks * 8 + tig;
                bf[nt][0] = p[0];
                bf[nt][1] = p[4];
            }
#pragma unroll
            for (int mt = 0; mt < 2; mt++)
#pragma unroll
                for (int nt = 0; nt < 8; nt++)
                    mma16(acc[mt][nt], a[mt], bf[nt]);
        }
        __syncthreads();
    }

    // Epilogue
#pragma unroll
    for (int mt = 0; mt < 2; mt++) {
#pragma unroll
        for (int i = 0; i < 2; i++) {
            const int m = m0 + wm + 16 * mt + g + 8 * i;
            if (m >= MTOT) continue;
            const int bq_ = m / NPAD, rq = m % NPAD;
#pragma unroll
            for (int nt = 0; nt < 8; nt++) {
                const int n = n0 + wn + nt * 8 + 2 * tig;
                float v0 = acc[mt][nt][2 * i + 0] + bias[n];
                float v1 = acc[mt][nt][2 * i + 1] + bias[n + 1];
                if (mode == 0) {          // q pre-scaled (log2-domain softmax)
                    const int hh = n >> 6, d = n & 63;
                    *(uint32_t*)&g_qh[(((size_t)bq_ * NH + hh) * NPAD + rq) * HD + d] =
                        f2h2(v0 * QSCALE, v1 * QSCALE);
                } else if (mode == 1) {   // k, pair-permuted within 64-half row
                    const int hh = n >> 6, d = n & 63;
                    const int dp = pperm(d >> 1) << 1;
                    *(uint32_t*)&g_kh[(((size_t)bq_ * NH + hh) * NPAD + rq) * HD + dp] =
                        f2h2(v0, v1);
                } else if (mode == 2) {   // v transposed [d][key], key pair-permuted
                    const int hh = n >> 6, d = n & 63;
                    const int rqp = (rq & ~63) | (pperm((rq & 63) >> 1) << 1) | (rq & 1);
                    g_vt[(((size_t)bq_ * NH + hh) * HD + d)     * VPITCH + rqp] = __float2half(v0);
                    g_vt[(((size_t)bq_ * NH + hh) * HD + d + 1) * VPITCH + rqp] = __float2half(v1);
                } else {                  // O-proj fp32 out
                    *reinterpret_cast<float2*>(&outp[(size_t)m * E_DIM + n]) =
                        make_float2(v0, v1);
                }
            }
        }
    }
}

// ---------------------------------------------------------------------------
// Flash attention, fp16 mma, wide-M warps: each warp owns 32 q-rows
// (2 m-tiles) sharing one set of K/V B-fragments -> fragment LDS per q-row
// halved. CTA: 128 q-rows, 128 threads (4 warps). 2-stage cp.async for
// K/V/bias/mask. Fixed-reference log2-domain softmax.
// ---------------------------------------------------------------------------
__global__ __launch_bounds__(128, 2) void attn_f16(const float* __restrict__ bias)
{
    extern __shared__ __align__(16) uint32_t sma[];
    const uint32_t sb = smem_u32(sma);

    const int tid  = threadIdx.x;
    const int lane = tid & 31, warp = tid >> 5;
    const int g = lane >> 2, tig = lane & 3;
    const int qt = blockIdx.x, h = blockIdx.y, b = blockIdx.z;
    const int bh = b * NH + h;
    const int qbase = qt * QTILE, slab = warp * 32;
    // per-thread rows: r[mt][i] = qbase + slab + g + 16*mt + 8*i
    const size_t biasEnd = (size_t)BB * NH * NPAD * NPAD * 4;

    // Q fragments for both m-tiles
    uint32_t qf[2][4][4];
#pragma unroll
    for (int mt = 0; mt < 2; mt++) {
        const int r0 = qbase + slab + 16 * mt + g;
        const int r1 = r0 + 8;
        const uint32_t* q0 = (const uint32_t*)(g_qh + ((size_t)bh * NPAD + r0) * HD);
        const uint32_t* q1 = (const uint32_t*)(g_qh + ((size_t)bh * NPAD + r1) * HD);
        const bool o0 = r0 < NPAD, o1 = r1 < NPAD;
#pragma unroll
        for (int kc = 0; kc < 4; kc++)
#pragma unroll
            for (int hf = 0; hf < 2; hf++) {
                const int u = 8 * kc + tig + 4 * hf;
                qf[mt][kc][2 * hf + 0] = o0 ? __ldg(&q0[u]) : 0u;
                qf[mt][kc][2 * hf + 1] = o1 ? __ldg(&q1[u]) : 0u;
            }
    }

    auto stage = [&](int buf, int kt) {
        const int kbase = kt * 64;
        const uint32_t base = sb + buf * STAGE_B;
        // K tile: 64 keys x 64 halves
#pragma unroll
        for (int it = 0; it < 4; it++) {
            const int idx = it * 128 + tid;
            const int key = idx >> 3, c = idx & 7;
            cpa16(base + key * (KV_STRIDE * 4) + c * 16,
                  g_kh + ((size_t)bh * NPAD + kbase + key) * HD + c * 8,
                  kbase + key < NPAD);
        }
        // V tile: 64 d x 64 keys
#pragma unroll
        for (int it = 0; it < 4; it++) {
            const int idx = it * 128 + tid;
            const int d = idx >> 3, c = idx & 7;
            cpa16(base + 10240 + d * (KV_STRIDE * 4) + c * 16,
                  g_vt + ((size_t)bh * HD + d) * VPITCH + kbase + c * 8,
                  true);
        }
        // bias tile: 128 rows x 17 aligned 16B chunks
#pragma unroll
        for (int it = 0; it < 17; it++) {
            const int idx = it * 128 + tid;   // 0..2175
            const int row = idx / 17, c = idx - row * 17;
            const int row_g = qbase + row;
            const size_t S = ((size_t)bh * NPAD + row_g) * NPAD + kbase;
            const size_t src = ((S * 4) & ~(size_t)15) + (size_t)c * 16;
            cpa16(base + 20480 + row * 272 + c * 16,
                  (const char*)bias + src,
                  (row_g < NPAD) && (src < biasEnd));
        }
        // mask: 2 words per row, 128 rows
        {
            const int row_g = qbase + tid;
            cpa8(base + 55296 + tid * 8,
                 g_mbits + ((size_t)b * NPAD + row_g) * MWORDS + 2 * kt,
                 row_g < NPAD);
        }
    };

    float lsum[2][2] = {{0.f, 0.f}, {0.f, 0.f}};
    float o[2][8][4];
#pragma unroll
    for (int mt = 0; mt < 2; mt++)
#pragma unroll
        for (int nt = 0; nt < 8; nt++)
#pragma unroll
            for (int e = 0; e < 4; e++) o[mt][nt][e] = 0.f;

    stage(0, 0); CP_COMMIT();

    for (int kt = 0; kt < 17; kt++) {
        const int kbase = kt * 64;
        if (kt < 16) { stage((kt + 1) & 1, kt + 1); CP_COMMIT(); }
        if (kt < 16) CP_WAIT1(); else CP_WAIT0();
        __syncthreads();

        const uint32_t* st = sma + (kt & 1) * STAGE_U32;
        const uint32_t* Ks = st;
        const uint32_t* Vt = st + 2560;
        const float*    Bs = (const float*)(st + 5120);
        const uint32_t* Mk = st + 13824;

        // S = Q K^T for both m-tiles; each K B-fragment feeds 2 mma
        float s[2][8][4];
#pragma unroll
        for (int mt = 0; mt < 2; mt++)
#pragma unroll
            for (int nt = 0; nt < 8; nt++)
#pragma unroll
                for (int e = 0; e < 4; e++) s[mt][nt][e] = -M2REF;
#pragma unroll
        for (int kc = 0; kc < 4; kc++) {
#pragma unroll
            for (int nt = 0; nt < 8; nt++) {
                const uint2 bb = *reinterpret_cast<const uint2*>(
                    &Ks[(8 * nt + g) * KV_STRIDE + kc * 8 + 2 * tig]);
                uint32_t bbr[2] = {bb.x, bb.y};
                mma16(s[0][nt], qf[0][kc], bbr);
                mma16(s[1][nt], qf[1][kc], bbr);
            }
        }

        // bias + mask + exp2, pack P fragments (af) per m-tile
        uint32_t af[2][4][4];
#pragma unroll
        for (int mt = 0; mt < 2; mt++) {
            const int lr0 = slab + 16 * mt + g;      // row-in-CTA for i=0
            const int row0 = qbase + lr0;
            const int row1 = row0 + 8;
            const uint2 mv0 = *reinterpret_cast<const uint2*>(&Mk[lr0 * 2]);
            const uint2 mv1 = *reinterpret_cast<const uint2*>(&Mk[(lr0 + 8) * 2]);
            const int sh0 = (int)((((size_t)bh * NPAD + row0) * NPAD + kbase) & 3);
            const int sh1 = (int)((((size_t)bh * NPAD + row1) * NPAD + kbase) & 3);
            const float* br0 = Bs + lr0 * 68 + sh0;
            const float* br1 = Bs + (lr0 + 8) * 68 + sh1;
#pragma unroll
            for (int nt = 0; nt < 8; nt++) {
                const int j = 8 * nt + 2 * tig;
                const uint32_t w0 = (j < 32) ? mv0.x : mv0.y;
                const uint32_t w1 = (j < 32) ? mv1.x : mv1.y;
                float v0 = __fmaf_rn(br0[j],     LOG2E, s[mt][nt][0]);
                float v1 = __fmaf_rn(br0[j + 1], LOG2E, s[mt][nt][1]);
                float v2 = __fmaf_rn(br1[j],     LOG2E, s[mt][nt][2]);
                float v3 = __fmaf_rn(br1[j + 1], LOG2E, s[mt][nt][3]);
                if (!((w0 >> (j & 31)) & 1u))       v0 = -1e30f;
                if (!((w0 >> ((j + 1) & 31)) & 1u)) v1 = -1e30f;
                if (!((w1 >> (j & 31)) & 1u))       v2 = -1e30f;
                if (!((w1 >> ((j + 1) & 31)) & 1u)) v3 = -1e30f;
                const float p0 = ex2(v0);
                const float p1 = ex2(v1);
                const float p2 = ex2(v2);
                const float p3 = ex2(v3);
                lsum[mt][0] += p0 + p1;
                lsum[mt][1] += p2 + p3;
                s[mt][nt][0] = p0; s[mt][nt][1] = p1;
                s[mt][nt][2] = p2; s[mt][nt][3] = p3;
            }
#pragma unroll
            for (int kc = 0; kc < 4; kc++) {
                af[mt][kc][0] = f2h2(s[mt][2 * kc][0],     s[mt][2 * kc][1]);
                af[mt][kc][1] = f2h2(s[mt][2 * kc][2],     s[mt][2 * kc][3]);
                af[mt][kc][2] = f2h2(s[mt][2 * kc + 1][0], s[mt][2 * kc + 1][1]);
                af[mt][kc][3] = f2h2(s[mt][2 * kc + 1][2], s[mt][2 * kc + 1][3]);
            }
        }

        // O += P V ; each V B-fragment feeds 2 mma
#pragma unroll
        for (int kc = 0; kc < 4; kc++) {
#pragma unroll
            for (int nt = 0; nt < 8; nt++) {
                const uint2 bb = *reinterpret_cast<const uint2*>(
                    &Vt[(8 * nt + g) * KV_STRIDE + kc * 8 + 2 * tig]);
                uint32_t bbr[2] = {bb.x, bb.y};
                mma16(o[0][nt], af[0][kc], bbr);
                mma16(o[1][nt], af[1][kc], bbr);
            }
        }
        __syncthreads();
    }

    // quad-reduce row sums, normalize, store
    __half* ob = g_atth + (size_t)b * NPAD * E_DIM + h * HD;
#pragma unroll
    for (int mt = 0; mt < 2; mt++) {
#pragma unroll
        for (int i = 0; i < 2; i++) {
            float l = lsum[mt][i];
            l += __shfl_xor_sync(0xffffffffu, l, 1);
            l += __shfl_xor_sync(0xffffffffu, l, 2);
            lsum[mt][i] = (l > 0.f) ? 1.f / l : 0.f;
        }
        const int r0 = qbase + slab + 16 * mt + g;
        const int r1 = r0 + 8;
#pragma unroll
        for (int nt = 0; nt < 8; nt++) {
            const int d = nt * 8 + 2 * tig;
            if (r0 < NPAD)
                *(uint32_t*)&ob[(size_t)r0 * E_DIM + d] =
                    f2h2(o[mt][nt][0] * lsum[mt][0], o[mt][nt][1] * lsum[mt][0]);
            if (r1 < NPAD)
                *(uint32_t*)&ob[(size_t)r1 * E_DIM + d] =
                    f2h2(o[mt][nt][2] * lsum[mt][1], o[mt][nt][3] * lsum[mt][1]);
        }
    }
}

// ---------------------------------------------------------------------------
extern "C" void kernel_launch(void* const* d_in, const int* in_sizes, int n_in,
                              void* d_out, int out_size)
{
    const float* x  = (const float*)d_in[0];
    const float* ab = (const float*)d_in[1];
    const int*   pm = (const int*)d_in[2];
    const float* Wq = (const float*)d_in[3];
    const float* bq = (const float*)d_in[4];
    const float* Wk = (const float*)d_in[5];
    const float* bk = (const float*)d_in[6];
    const float* Wv = (const float*)d_in[7];
    const float* bv = (const float*)d_in[8];
    const float* Wo = (const float*)d_in[9];
    const float* bo = (const float*)d_in[10];
    float* out = (float*)d_out;

    cudaFuncSetAttribute(gemm_f16, cudaFuncAttributeMaxDynamicSharedMemorySize, 73728);
    cudaFuncSetAttribute(attn_f16, cudaFuncAttributeMaxDynamicSharedMemorySize, 2 * STAGE_B);

    prep_all<<<(PREP_TOTAL + 255) / 256, 256>>>(x, Wq, Wk, Wv, Wo, pm);

    gemm_f16<<<dim3(4, 65, 3), 256, 73728>>>(bq, bk, bv, nullptr, 1);

    attn_f16<<<dim3(9, NH, BB), 128, 2 * STAGE_B>>>(ab);

    gemm_f16<<<dim3(4, 65, 1), 256, 73728>>>(bo, nullptr, nullptr, out, 0);
}

// round 15
// speedup vs baseline: 1.0256x; 1.0256x over previous
#include <cuda_runtime.h>
#include <cuda_fp16.h>
#include <cstdint>

#define E_DIM 512
#define NH    8
#define HD    64
#define BB    8
#define NPAD  1025
#define NTOK  1024
#define MTOT  (BB * NPAD)   // 8200
#define MWORDS 34
#define VPITCH 1088         // 17*64: padded key count for transposed V (halves)

// softmax in log2 domain: exp(x) = exp2(x * LOG2E); fixed reference M2 = 16
#define LOG2E 1.44269504f
#define QSCALE (0.125f * LOG2E)
#define M2REF 16.0f

// attention K/V smem row stride 40 u32 (== 8 mod 32 -> conflict-free LDS.64)
#define KV_STRIDE 40
// attention stage (u32): Ks@0 [64][40], Vt@2560 [64][40], Bs@5120 [64][68]f32,
//   Mk@9472 [64][2] -> 9600 u32 = 38400 B per stage, 2 stages.
#define STAGE_U32 9600
#define STAGE_B   38400

// gemm smem: stride 40 u32 rows; A[128][40] + W[128][40] per stage = 40960 B,
// 2 stages = 81920 B.
#define GSTRIDE 40
#define GEMM_SMEM 81920

// fragment-pair permutation within a 32-u32 (64-half) group:
// source word p lands at pperm(p); consumer reads {8kc+2tig, 8kc+2tig+1}
// to get old {8kc+tig, 8kc+tig+4}.
__host__ __device__ __forceinline__ int pperm(int p) {
    return ((p >> 3) << 3) + ((p & 3) << 1) + ((p >> 2) & 1);
}

// Scratch (allocation-free rule: __device__ globals)
__device__ __half   g_xh [MTOT * E_DIM];              // pair-permuted columns
__device__ __half   g_wh [4 * E_DIM * E_DIM];         // pair-permuted columns
__device__ __half   g_qh [BB * NH * NPAD * HD];       // q * 0.125*log2e (unpermuted)
__device__ __half   g_kh [BB * NH * NPAD * HD];       // [b,h][row][d] (pair-permuted)
__device__ __half   g_vt [BB * NH * HD * VPITCH];     // [b,h][d][key] (pair-permuted)
__device__ __half   g_atth[MTOT * E_DIM];             // [b,row][h*64+d] (pair-permuted)
__device__ uint32_t g_mbits[BB * NPAD * MWORDS];

// ---------------------------------------------------------------------------
__device__ __forceinline__ uint32_t f2h2(float lo, float hi) {
    uint32_t r;
    asm("cvt.rn.f16x2.f32 %0, %1, %2;" : "=r"(r) : "f"(hi), "f"(lo));
    return r;
}
__device__ __forceinline__ float ex2(float x) {
    float r;
    asm("ex2.approx.ftz.f32 %0, %1;" : "=f"(r) : "f"(x));
    return r;
}
__device__ __forceinline__ void mma16(float* c, const uint32_t* a, const uint32_t* b) {
    asm volatile(
        "mma.sync.aligned.m16n8k16.row.col.f32.f16.f16.f32 "
        "{%0,%1,%2,%3}, {%4,%5,%6,%7}, {%8,%9}, {%0,%1,%2,%3};\n"
        : "+f"(c[0]), "+f"(c[1]), "+f"(c[2]), "+f"(c[3])
        : "r"(a[0]), "r"(a[1]), "r"(a[2]), "r"(a[3]), "r"(b[0]), "r"(b[1]));
}
__device__ __forceinline__ uint32_t smem_u32(const void* p) {
    uint32_t a;
    asm("{.reg .u64 t; cvta.to.shared.u64 t, %1; cvt.u32.u64 %0, t;}" : "=r"(a) : "l"(p));
    return a;
}
__device__ __forceinline__ void cpa16(uint32_t dst, const void* src, bool ok) {
    asm volatile("cp.async.ca.shared.global [%0], [%1], 16, %2;"
                 :: "r"(dst), "l"(src), "r"(ok ? 16 : 0));
}
__device__ __forceinline__ void cpa8(uint32_t dst, const void* src, bool ok) {
    asm volatile("cp.async.ca.shared.global [%0], [%1], 8, %2;"
                 :: "r"(dst), "l"(src), "r"(ok ? 8 : 0));
}
#define CP_COMMIT() asm volatile("cp.async.commit_group;")
#define CP_WAIT1()  asm volatile("cp.async.wait_group 1;")
#define CP_WAIT0()  asm volatile("cp.async.wait_group 0;")

// ---------------------------------------------------------------------------
// Fused prep: x->half (pair-permuted), W->half (pair-permuted), g_vt pad zero,
// pack mask bits.
// ---------------------------------------------------------------------------
#define XCNT (MTOT * E_DIM)                 // 4,198,400
#define WCNT (4 * E_DIM * E_DIM)            // 1,048,576
#define PADCNT (BB * NH * HD * 63)          // 258,048
#define MASKCNT (BB * NPAD * MWORDS)        // 278,800
#define PREP_TOTAL (XCNT + WCNT + PADCNT + MASKCNT)
__global__ void prep_all(const float* __restrict__ x,
                         const float* __restrict__ Wq, const float* __restrict__ Wk,
                         const float* __restrict__ Wv, const float* __restrict__ Wo,
                         const int* __restrict__ pm)
{
    int idx = blockIdx.x * 256 + threadIdx.x;
    if (idx < XCNT) {
        const int row = idx >> 9, c = idx & 511;
        const int p = c >> 1, lo = c & 1;
        const int pd = (p & ~31) | pperm(p & 31);
        g_xh[((size_t)row << 9) + (pd << 1) + lo] = __float2half(x[idx]);
    } else if (idx < XCNT + WCNT) {
        int wi = idx - XCNT;
        int m = wi >> 18, off = wi & 262143;
        const float* W = (m == 0) ? Wq : (m == 1) ? Wk : (m == 2) ? Wv : Wo;
        const int row = wi >> 9, c = wi & 511;
        const int p = c >> 1, lo = c & 1;
        const int pd = (p & ~31) | pperm(p & 31);
        g_wh[((size_t)row << 9) + (pd << 1) + lo] = __float2half(W[off]);
    } else if (idx < XCNT + WCNT + PADCNT) {
        int e = idx - XCNT - WCNT;
        int p = e % 63, rest = e / 63;   // keys 1025..1087 (stored order)
        g_vt[(size_t)rest * VPITCH + NPAD + p] = __float2half(0.f);
    } else if (idx < PREP_TOTAL) {
        int mi = idx - XCNT - WCNT - PADCNT;
        int w = mi % MWORDS;
        int row = (mi / MWORDS) % NPAD;
        int b = mi / (MWORDS * NPAD);
        uint32_t bits = 0;
        for (int i = 0; i < 32; i++) {
            int col = w * 32 + i;
            if (col >= NPAD) break;
            bool keep;
            if (row == 0 || col == 0) keep = true;
            else keep = __ldg(&pm[(b * NTOK + row - 1) * NTOK + col - 1]) != 0;
            if (keep) bits |= (1u << i);
        }
        g_mbits[mi] = bits;
    }
}

// ---------------------------------------------------------------------------
// fp16 GEMM: C = A @ W^T + b.  128x128 CTA tile, K-chunk 64, 2-stage cp.async.
// A and W are pair-permuted in gmem -> all fragment loads are LDS.64,
// stride GSTRIDE=40 u32 keeps them bank-conflict-free.
// qkv=1: mode = blockIdx.z (0:q scaled, 1:k permuted, 2:v transposed+permuted)
// qkv=0: O-proj, fp32 out (unpermuted).
// ---------------------------------------------------------------------------
__global__ __launch_bounds__(256) void gemm_f16(
    const float* __restrict__ b0, const float* __restrict__ b1,
    const float* __restrict__ b2, float* __restrict__ outp, int qkv)
{
    extern __shared__ __align__(16) __half smg[];
    const uint32_t sb = smem_u32(smg);
    const uint32_t* smu = (const uint32_t*)smg;

    const int mode = qkv ? blockIdx.z : 3;
    const __half* A = qkv ? g_xh : g_atth;
    const __half* W = g_wh + (size_t)mode * E_DIM * E_DIM;
    const float* bias = (mode == 0) ? b0 : (mode == 1) ? b1 : (mode == 2) ? b2 : b0;

    const int tid = threadIdx.x;
    const int lane = tid & 31, warp = tid >> 5;
    const int g = lane >> 2, tig = lane & 3;
    const int wm = (warp & 3) * 32, wn = (warp >> 2) * 64;
    const int m0 = blockIdx.y * 128, n0 = blockIdx.x * 128;

    // stage: A[128][40] @ buf*10240 u32, W[128][40] @ +5120 u32
    auto stage = [&](int buf, int kc) {
        const uint32_t abase = sb + buf * 40960;
        const uint32_t wbase = abase + 20480;
#pragma unroll
        for (int it = 0; it < 4; it++) {
            const int idx = it * 256 + tid;          // 0..1023
            const int row = idx >> 3, c = idx & 7;
            const int m = m0 + row;
            cpa16(abase + row * 160 + c * 16,
                  A + (size_t)m * E_DIM + kc + c * 8, m < MTOT);
        }
#pragma unroll
        for (int it = 0; it < 4; it++) {
            const int idx = it * 256 + tid;
            const int row = idx >> 3, c = idx & 7;
            cpa16(wbase + row * 160 + c * 16,
                  W + (size_t)(n0 + row) * E_DIM + kc + c * 8, true);
        }
    };

    float acc[2][8][4];
#pragma unroll
    for (int mt = 0; mt < 2; mt++)
#pragma unroll
        for (int nt = 0; nt < 8; nt++)
#pragma unroll
            for (int e = 0; e < 4; e++) acc[mt][nt][e] = 0.f;

    stage(0, 0); CP_COMMIT();

    for (int ch = 0; ch < 8; ch++) {
        if (ch < 7) { stage((ch + 1) & 1, (ch + 1) * 64); CP_COMMIT(); }
        if (ch < 7) CP_WAIT1(); else CP_WAIT0();
        __syncthreads();

        const uint32_t* Au = smu + (ch & 1) * 10240;
        const uint32_t* Wu = Au + 5120;
#pragma unroll
        for (int ks = 0; ks < 4; ks++) {
            uint32_t a[2][4];
#pragma unroll
            for (int mt = 0; mt < 2; mt++) {
                const int r = wm + 16 * mt + g;
                const uint2 alo = *reinterpret_cast<const uint2*>(
                    &Au[r * GSTRIDE + ks * 8 + 2 * tig]);
                const uint2 ahi = *reinterpret_cast<const uint2*>(
                    &Au[(r + 8) * GSTRIDE + ks * 8 + 2 * tig]);
                a[mt][0] = alo.x; a[mt][1] = ahi.x;
                a[mt][2] = alo.y; a[mt][3] = ahi.y;
            }
            uint32_t bf[8][2];
#pragma unroll
            for (int nt = 0; nt < 8; nt++) {
                const uint2 bb = *reinterpret_cast<const uint2*>(
                    &Wu[(wn + 8 * nt + g) * GSTRIDE + ks * 8 + 2 * tig]);
                bf[nt][0] = bb.x; bf[nt][1] = bb.y;
            }
#pragma unroll
            for (int mt = 0; mt < 2; mt++)
#pragma unroll
                for (int nt = 0; nt < 8; nt++)
                    mma16(acc[mt][nt], a[mt], bf[nt]);
        }
        __syncthreads();
    }

    // Epilogue
#pragma unroll
    for (int mt = 0; mt < 2; mt++) {
#pragma unroll
        for (int i = 0; i < 2; i++) {
            const int m = m0 + wm + 16 * mt + g + 8 * i;
            if (m >= MTOT) continue;
            const int bq_ = m / NPAD, rq = m % NPAD;
#pragma unroll
            for (int nt = 0; nt < 8; nt++) {
                const int n = n0 + wn + nt * 8 + 2 * tig;
                float v0 = acc[mt][nt][2 * i + 0] + bias[n];
                float v1 = acc[mt][nt][2 * i + 1] + bias[n + 1];
                if (mode == 0) {          // q pre-scaled (log2-domain softmax)
                    const int hh = n >> 6, d = n & 63;
                    *(uint32_t*)&g_qh[(((size_t)bq_ * NH + hh) * NPAD + rq) * HD + d] =
                        f2h2(v0 * QSCALE, v1 * QSCALE);
                } else if (mode == 1) {   // k, pair-permuted within 64-half row
                    const int hh = n >> 6, d = n & 63;
                    const int dp = pperm(d >> 1) << 1;
                    *(uint32_t*)&g_kh[(((size_t)bq_ * NH + hh) * NPAD + rq) * HD + dp] =
                        f2h2(v0, v1);
                } else if (mode == 2) {   // v transposed [d][key], key pair-permuted
                    const int hh = n >> 6, d = n & 63;
                    const int rqp = (rq & ~63) | (pperm((rq & 63) >> 1) << 1) | (rq & 1);
                    g_vt[(((size_t)bq_ * NH + hh) * HD + d)     * VPITCH + rqp] = __float2half(v0);
                    g_vt[(((size_t)bq_ * NH + hh) * HD + d + 1) * VPITCH + rqp] = __float2half(v1);
                } else {                  // O-proj fp32 out
                    *reinterpret_cast<float2*>(&outp[(size_t)m * E_DIM + n]) =
                        make_float2(v0, v1);
                }
            }
        }
    }
}

// ---------------------------------------------------------------------------
// Flash attention (R13 structure), fp16 mma, 2-stage cp.async pipeline.
// Fixed-reference log2-domain softmax. K/V pair-permuted -> LDS.64 fragments,
// KV_STRIDE=40 conflict-free. Epilogue writes g_atth pair-permuted for the
// O-proj gemm's A-fragment LDS.64 loads.
// ---------------------------------------------------------------------------
__global__ __launch_bounds__(128, 3) void attn_f16(const float* __restrict__ bias)
{
    extern __shared__ __align__(16) uint32_t sma[];
    const uint32_t sb = smem_u32(sma);

    const int tid  = threadIdx.x;
    const int lane = tid & 31, warp = tid >> 5;
    const int g = lane >> 2, tig = lane & 3;
    const int qt = blockIdx.x, h = blockIdx.y, b = blockIdx.z;
    const int bh = b * NH + h;
    const int qbase = qt * 64, slab = warp * 16;
    const int row0 = qbase + slab + g;
    const int row1 = row0 + 8;
    const bool ok0 = row0 < NPAD, ok1 = row1 < NPAD;
    const size_t biasEnd = (size_t)BB * NH * NPAD * NPAD * 4;

    // Q fragments (half2 direct from gmem; q layout unpermuted)
    uint32_t qf[4][4];
    {
        const uint32_t* q0 = (const uint32_t*)(g_qh + ((size_t)bh * NPAD + row0) * HD);
        const uint32_t* q1 = (const uint32_t*)(g_qh + ((size_t)bh * NPAD + row1) * HD);
#pragma unroll
        for (int kc = 0; kc < 4; kc++)
#pragma unroll
            for (int hf = 0; hf < 2; hf++) {
                const int u = 8 * kc + tig + 4 * hf;
                qf[kc][2 * hf + 0] = ok0 ? __ldg(&q0[u]) : 0u;
                qf[kc][2 * hf + 1] = ok1 ? __ldg(&q1[u]) : 0u;
            }
    }

    auto stage = [&](int buf, int kt) {
        const int kbase = kt * 64;
        const uint32_t base = sb + buf * STAGE_B;
#pragma unroll
        for (int it = 0; it < 4; it++) {
            const int idx = it * 128 + tid;
            const int key = idx >> 3, c = idx & 7;
            cpa16(base + key * (KV_STRIDE * 4) + c * 16,
                  g_kh + ((size_t)bh * NPAD + kbase + key) * HD + c * 8,
                  kbase + key < NPAD);
        }
#pragma unroll
        for (int it = 0; it < 4; it++) {
            const int idx = it * 128 + tid;
            const int d = idx >> 3, c = idx & 7;
            cpa16(base + 10240 + d * (KV_STRIDE * 4) + c * 16,
                  g_vt + ((size_t)bh * HD + d) * VPITCH + kbase + c * 8,
                  true);
        }
#pragma unroll
        for (int it = 0; it < 9; it++) {
            const int idx = it * 128 + tid;
            if (idx < 1088) {
                const int row = idx / 17, c = idx - row * 17;
                const int row_g = qbase + row;
                const size_t S = ((size_t)bh * NPAD + row_g) * NPAD + kbase;
                const size_t src = ((S * 4) & ~(size_t)15) + (size_t)c * 16;
                cpa16(base + 20480 + row * 272 + c * 16,
                      (const char*)bias + src,
                      (row_g < NPAD) && (src < biasEnd));
            }
        }
        if (tid < 64) {
            const int row_g = qbase + tid;
            cpa8(base + 37888 + tid * 8,
                 g_mbits + ((size_t)b * NPAD + row_g) * MWORDS + 2 * kt,
                 row_g < NPAD);
        }
    };

    float lsum[2] = {0.f, 0.f};
    float o[8][4];
#pragma unroll
    for (int nt = 0; nt < 8; nt++)
#pragma unroll
        for (int e = 0; e < 4; e++) o[nt][e] = 0.f;

    stage(0, 0); CP_COMMIT();

    for (int kt = 0; kt < 17; kt++) {
        const int kbase = kt * 64;
        if (kt < 16) { stage((kt + 1) & 1, kt + 1); CP_COMMIT(); }
        if (kt < 16) CP_WAIT1(); else CP_WAIT0();
        __syncthreads();

        const uint32_t* st = sma + (kt & 1) * STAGE_U32;
        const uint32_t* Ks = st;
        const uint32_t* Vt = st + 2560;
        const float*    Bs = (const float*)(st + 5120);
        const uint32_t* Mk = st + 9472;

        // S = Q K^T (accumulators pre-seeded with -M2REF); LDS.64 fragments
        float s[8][4];
#pragma unroll
        for (int nt = 0; nt < 8; nt++)
#pragma unroll
            for (int e = 0; e < 4; e++) s[nt][e] = -M2REF;
#pragma unroll
        for (int kc = 0; kc < 4; kc++) {
#pragma unroll
            for (int nt = 0; nt < 8; nt++) {
                const uint2 bb = *reinterpret_cast<const uint2*>(
                    &Ks[(8 * nt + g) * KV_STRIDE + kc * 8 + 2 * tig]);
                uint32_t bbr[2] = {bb.x, bb.y};
                mma16(s[nt], qf[kc], bbr);
            }
        }

        // bias (log2 domain, single FMA) + mask
        const uint2 mv0 = *reinterpret_cast<const uint2*>(&Mk[(slab + g) * 2]);
        const uint2 mv1 = *reinterpret_cast<const uint2*>(&Mk[(slab + g + 8) * 2]);
        const int sh0 = (int)((((size_t)bh * NPAD + row0) * NPAD + kbase) & 3);
        const int sh1 = (int)((((size_t)bh * NPAD + row1) * NPAD + kbase) & 3);
        const float* br0 = Bs + (slab + g) * 68 + sh0;
        const float* br1 = Bs + (slab + g + 8) * 68 + sh1;
#pragma unroll
        for (int nt = 0; nt < 8; nt++) {
            const int j = 8 * nt + 2 * tig;
            const uint32_t w0 = (j < 32) ? mv0.x : mv0.y;
            const uint32_t w1 = (j < 32) ? mv1.x : mv1.y;
            float v0 = __fmaf_rn(br0[j],     LOG2E, s[nt][0]);
            float v1 = __fmaf_rn(br0[j + 1], LOG2E, s[nt][1]);
            float v2 = __fmaf_rn(br1[j],     LOG2E, s[nt][2]);
            float v3 = __fmaf_rn(br1[j + 1], LOG2E, s[nt][3]);
            if (!((w0 >> (j & 31)) & 1u))       v0 = -1e30f;
            if (!((w0 >> ((j + 1) & 31)) & 1u)) v1 = -1e30f;
            if (!((w1 >> (j & 31)) & 1u))       v2 = -1e30f;
            if (!((w1 >> ((j + 1) & 31)) & 1u)) v3 = -1e30f;
            s[nt][0] = v0; s[nt][1] = v1; s[nt][2] = v2; s[nt][3] = v3;
        }

        // p = exp2(v); per-thread partial row sums (reduced once at end)
#pragma unroll
        for (int nt = 0; nt < 8; nt++) {
            float p0 = ex2(s[nt][0]);
            float p1 = ex2(s[nt][1]);
            float p2 = ex2(s[nt][2]);
            float p3 = ex2(s[nt][3]);
            s[nt][0] = p0; s[nt][1] = p1; s[nt][2] = p2; s[nt][3] = p3;
            lsum[0] += p0 + p1;
            lsum[1] += p2 + p3;
        }

        // O += P V ; LDS.64 fragments
#pragma unroll
        for (int kc = 0; kc < 4; kc++) {
            uint32_t af[4];
            af[0] = f2h2(s[2 * kc][0],     s[2 * kc][1]);
            af[1] = f2h2(s[2 * kc][2],     s[2 * kc][3]);
            af[2] = f2h2(s[2 * kc + 1][0], s[2 * kc + 1][1]);
            af[3] = f2h2(s[2 * kc + 1][2], s[2 * kc + 1][3]);
#pragma unroll
            for (int nt = 0; nt < 8; nt++) {
                const uint2 bb = *reinterpret_cast<const uint2*>(
                    &Vt[(8 * nt + g) * KV_STRIDE + kc * 8 + 2 * tig]);
                uint32_t bbr[2] = {bb.x, bb.y};
                mma16(o[nt], af, bbr);
            }
        }
        __syncthreads();
    }

    // quad-reduce row sums once
    lsum[0] += __shfl_xor_sync(0xffffffffu, lsum[0], 1);
    lsum[0] += __shfl_xor_sync(0xffffffffu, lsum[0], 2);
    lsum[1] += __shfl_xor_sync(0xffffffffu, lsum[1], 1);
    lsum[1] += __shfl_xor_sync(0xffffffffu, lsum[1], 2);

    // epilogue: normalize + store half to g_atth, pair-permuted within head
    const float inv0 = (lsum[0] > 0.f) ? 1.f / lsum[0] : 0.f;
    const float inv1 = (lsum[1] > 0.f) ? 1.f / lsum[1] : 0.f;
    __half* ob = g_atth + (size_t)b * NPAD * E_DIM + h * HD;
#pragma unroll
    for (int nt = 0; nt < 8; nt++) {
        const int d = nt * 8 + 2 * tig;
        const int dp = pperm(d >> 1) << 1;   // permuted column for O-proj LDS.64
        if (ok0)
            *(uint32_t*)&ob[(size_t)row0 * E_DIM + dp] = f2h2(o[nt][0] * inv0, o[nt][1] * inv0);
        if (ok1)
            *(uint32_t*)&ob[(size_t)row1 * E_DIM + dp] = f2h2(o[nt][2] * inv1, o[nt][3] * inv1);
    }
}

// ---------------------------------------------------------------------------
extern "C" void kernel_launch(void* const* d_in, const int* in_sizes, int n_in,
                              void* d_out, int out_size)
{
    const float* x  = (const float*)d_in[0];
    const float* ab = (const float*)d_in[1];
    const int*   pm = (const int*)d_in[2];
    const float* Wq = (const float*)d_in[3];
    const float* bq = (const float*)d_in[4];
    const float* Wk = (const float*)d_in[5];
    const float* bk = (const float*)d_in[6];
    const float* Wv = (const float*)d_in[7];
    const float* bv = (const float*)d_in[8];
    const float* Wo = (const float*)d_in[9];
    const float* bo = (const float*)d_in[10];
    float* out = (float*)d_out;

    cudaFuncSetAttribute(gemm_f16, cudaFuncAttributeMaxDynamicSharedMemorySize, GEMM_SMEM);
    cudaFuncSetAttribute(attn_f16, cudaFuncAttributeMaxDynamicSharedMemorySize, 2 * STAGE_B);

    prep_all<<<(PREP_TOTAL + 255) / 256, 256>>>(x, Wq, Wk, Wv, Wo, pm);

    gemm_f16<<<dim3(4, 65, 3), 256, GEMM_SMEM>>>(bq, bk, bv, nullptr, 1);

    attn_f16<<<dim3(17, NH, BB), 128, 2 * STAGE_B>>>(ab);

    gemm_f16<<<dim3(4, 65, 1), 256, GEMM_SMEM>>>(bo, nullptr, nullptr, out, 0);
}

// round 16
// speedup vs baseline: 1.1951x; 1.1652x over previous
#include <cuda_runtime.h>
#include <cuda_fp16.h>
#include <cstdint>

#define E_DIM 512
#define NH    8
#define HD    64
#define BB    8
#define NPAD  1025
#define NTOK  1024
#define MTOT  (BB * NPAD)   // 8200
#define MWORDS 34
#define VPITCH 1088         // 17*64: padded key count for transposed V (halves)

// softmax in log2 domain: exp(x) = exp2(x * LOG2E); fixed reference M2 = 16
#define LOG2E 1.44269504f
#define QSCALE (0.125f * LOG2E)
#define M2REF 16.0f

// attention K/V smem row stride 40 u32 (== 8 mod 32 -> conflict-free LDS.64)
#define KV_STRIDE 40
// attention stage (u32): Ks@0 [64][40], Vt@2560 [64][40], Bs@5120 [64][68]f32,
//   Mk@9472 [64][2] -> 9600 u32 = 38400 B per stage, 2 stages.
#define STAGE_U32 9600
#define STAGE_B   38400

// gemm smem: stride 40 u32 rows; A[128][40] + W[128][40] per stage = 40960 B,
// 2 stages = 81920 B.
#define GSTRIDE 40
#define GEMM_SMEM 81920

// fragment-pair permutation within a 32-u32 (64-half) group:
// source word p lands at pperm(p); consumer reads {8kc+2tig, 8kc+2tig+1}
// to get old {8kc+tig, 8kc+tig+4}.
__host__ __device__ __forceinline__ int pperm(int p) {
    return ((p >> 3) << 3) + ((p & 3) << 1) + ((p >> 2) & 1);
}

// Scratch (allocation-free rule: __device__ globals)
__device__ __half   g_xh [MTOT * E_DIM];              // pair-permuted columns
__device__ __half   g_wh [4 * E_DIM * E_DIM];         // pair-permuted columns
__device__ __half   g_qh [BB * NH * NPAD * HD];       // q * 0.125*log2e (unpermuted)
__device__ __half   g_kh [BB * NH * NPAD * HD];       // [b,h][row][d] (pair-permuted)
__device__ __half   g_vt [BB * NH * HD * VPITCH];     // [b,h][d][key] (pair-permuted)
__device__ __half   g_atth[MTOT * E_DIM];             // [b,row][h*64+d] (pair-permuted)
__device__ uint32_t g_mbits[BB * NPAD * MWORDS];

// ---------------------------------------------------------------------------
__device__ __forceinline__ uint32_t f2h2(float lo, float hi) {
    uint32_t r;
    asm("cvt.rn.f16x2.f32 %0, %1, %2;" : "=r"(r) : "f"(hi), "f"(lo));
    return r;
}
__device__ __forceinline__ float ex2(float x) {
    float r;
    asm("ex2.approx.ftz.f32 %0, %1;" : "=f"(r) : "f"(x));
    return r;
}
__device__ __forceinline__ void mma16(float* c, const uint32_t* a, const uint32_t* b) {
    asm volatile(
        "mma.sync.aligned.m16n8k16.row.col.f32.f16.f16.f32 "
        "{%0,%1,%2,%3}, {%4,%5,%6,%7}, {%8,%9}, {%0,%1,%2,%3};\n"
        : "+f"(c[0]), "+f"(c[1]), "+f"(c[2]), "+f"(c[3])
        : "r"(a[0]), "r"(a[1]), "r"(a[2]), "r"(a[3]), "r"(b[0]), "r"(b[1]));
}
__device__ __forceinline__ uint32_t smem_u32(const void* p) {
    uint32_t a;
    asm("{.reg .u64 t; cvta.to.shared.u64 t, %1; cvt.u32.u64 %0, t;}" : "=r"(a) : "l"(p));
    return a;
}
__device__ __forceinline__ void cpa16(uint32_t dst, const void* src, bool ok) {
    asm volatile("cp.async.ca.shared.global [%0], [%1], 16, %2;"
                 :: "r"(dst), "l"(src), "r"(ok ? 16 : 0));
}
__device__ __forceinline__ void cpa8(uint32_t dst, const void* src, bool ok) {
    asm volatile("cp.async.ca.shared.global [%0], [%1], 8, %2;"
                 :: "r"(dst), "l"(src), "r"(ok ? 8 : 0));
}
#define CP_COMMIT() asm volatile("cp.async.commit_group;")
#define CP_WAIT1()  asm volatile("cp.async.wait_group 1;")
#define CP_WAIT0()  asm volatile("cp.async.wait_group 0;")

// ---------------------------------------------------------------------------
// Fused prep: x->half (pair-permuted), W->half (pair-permuted), g_vt pad zero,
// pack mask bits.
// ---------------------------------------------------------------------------
#define XCNT (MTOT * E_DIM)                 // 4,198,400
#define WCNT (4 * E_DIM * E_DIM)            // 1,048,576
#define PADCNT (BB * NH * HD * 63)          // 258,048
#define MASKCNT (BB * NPAD * MWORDS)        // 278,800
#define PREP_TOTAL (XCNT + WCNT + PADCNT + MASKCNT)
__global__ void prep_all(const float* __restrict__ x,
                         const float* __restrict__ Wq, const float* __restrict__ Wk,
                         const float* __restrict__ Wv, const float* __restrict__ Wo,
                         const int* __restrict__ pm)
{
    int idx = blockIdx.x * 256 + threadIdx.x;
    if (idx < XCNT) {
        const int row = idx >> 9, c = idx & 511;
        const int p = c >> 1, lo = c & 1;
        const int pd = (p & ~31) | pperm(p & 31);
        g_xh[((size_t)row << 9) + (pd << 1) + lo] = __float2half(x[idx]);
    } else if (idx < XCNT + WCNT) {
        int wi = idx - XCNT;
        int m = wi >> 18, off = wi & 262143;
        const float* W = (m == 0) ? Wq : (m == 1) ? Wk : (m == 2) ? Wv : Wo;
        const int row = wi >> 9, c = wi & 511;
        const int p = c >> 1, lo = c & 1;
        const int pd = (p & ~31) | pperm(p & 31);
        g_wh[((size_t)row << 9) + (pd << 1) + lo] = __float2half(W[off]);
    } else if (idx < XCNT + WCNT + PADCNT) {
        int e = idx - XCNT - WCNT;
        int p = e % 63, rest = e / 63;   // keys 1025..1087 (stored order)
        g_vt[(size_t)rest * VPITCH + NPAD + p] = __float2half(0.f);
    } else if (idx < PREP_TOTAL) {
        int mi = idx - XCNT - WCNT - PADCNT;
        int w = mi % MWORDS;
        int row = (mi / MWORDS) % NPAD;
        int b = mi / (MWORDS * NPAD);
        uint32_t bits = 0;
        for (int i = 0; i < 32; i++) {
            int col = w * 32 + i;
            if (col >= NPAD) break;
            bool keep;
            if (row == 0 || col == 0) keep = true;
            else keep = __ldg(&pm[(b * NTOK + row - 1) * NTOK + col - 1]) != 0;
            if (keep) bits |= (1u << i);
        }
        g_mbits[mi] = bits;
    }
}

// ---------------------------------------------------------------------------
// fp16 GEMM: C = A @ W^T + b.  128x128 CTA tile, K-chunk 64, 2-stage cp.async.
// A and W pair-permuted in gmem -> LDS.64 fragments, GSTRIDE=40 conflict-free.
// qkv=1: mode = blockIdx.z (0:q scaled, 1:k permuted, 2:v transposed+permuted)
// qkv=0: O-proj, fp32 out (unpermuted).
// ---------------------------------------------------------------------------
__global__ __launch_bounds__(256) void gemm_f16(
    const float* __restrict__ b0, const float* __restrict__ b1,
    const float* __restrict__ b2, float* __restrict__ outp, int qkv)
{
    extern __shared__ __align__(16) __half smg[];
    const uint32_t sb = smem_u32(smg);
    const uint32_t* smu = (const uint32_t*)smg;

    const int mode = qkv ? blockIdx.z : 3;
    const __half* A = qkv ? g_xh : g_atth;
    const __half* W = g_wh + (size_t)mode * E_DIM * E_DIM;
    const float* bias = (mode == 0) ? b0 : (mode == 1) ? b1 : (mode == 2) ? b2 : b0;

    const int tid = threadIdx.x;
    const int lane = tid & 31, warp = tid >> 5;
    const int g = lane >> 2, tig = lane & 3;
    const int wm = (warp & 3) * 32, wn = (warp >> 2) * 64;
    const int m0 = blockIdx.y * 128, n0 = blockIdx.x * 128;

    auto stage = [&](int buf, int kc) {
        const uint32_t abase = sb + buf * 40960;
        const uint32_t wbase = abase + 20480;
#pragma unroll
        for (int it = 0; it < 4; it++) {
            const int idx = it * 256 + tid;          // 0..1023
            const int row = idx >> 3, c = idx & 7;
            const int m = m0 + row;
            cpa16(abase + row * 160 + c * 16,
                  A + (size_t)m * E_DIM + kc + c * 8, m < MTOT);
        }
#pragma unroll
        for (int it = 0; it < 4; it++) {
            const int idx = it * 256 + tid;
            const int row = idx >> 3, c = idx & 7;
            cpa16(wbase + row * 160 + c * 16,
                  W + (size_t)(n0 + row) * E_DIM + kc + c * 8, true);
        }
    };

    float acc[2][8][4];
#pragma unroll
    for (int mt = 0; mt < 2; mt++)
#pragma unroll
        for (int nt = 0; nt < 8; nt++)
#pragma unroll
            for (int e = 0; e < 4; e++) acc[mt][nt][e] = 0.f;

    stage(0, 0); CP_COMMIT();

    for (int ch = 0; ch < 8; ch++) {
        if (ch < 7) { stage((ch + 1) & 1, (ch + 1) * 64); CP_COMMIT(); }
        if (ch < 7) CP_WAIT1(); else CP_WAIT0();
        __syncthreads();

        const uint32_t* Au = smu + (ch & 1) * 10240;
        const uint32_t* Wu = Au + 5120;
#pragma unroll
        for (int ks = 0; ks < 4; ks++) {
            uint32_t a[2][4];
#pragma unroll
            for (int mt = 0; mt < 2; mt++) {
                const int r = wm + 16 * mt + g;
                const uint2 alo = *reinterpret_cast<const uint2*>(
                    &Au[r * GSTRIDE + ks * 8 + 2 * tig]);
                const uint2 ahi = *reinterpret_cast<const uint2*>(
                    &Au[(r + 8) * GSTRIDE + ks * 8 + 2 * tig]);
                a[mt][0] = alo.x; a[mt][1] = ahi.x;
                a[mt][2] = alo.y; a[mt][3] = ahi.y;
            }
            uint32_t bf[8][2];
#pragma unroll
            for (int nt = 0; nt < 8; nt++) {
                const uint2 bb = *reinterpret_cast<const uint2*>(
                    &Wu[(wn + 8 * nt + g) * GSTRIDE + ks * 8 + 2 * tig]);
                bf[nt][0] = bb.x; bf[nt][1] = bb.y;
            }
#pragma unroll
            for (int mt = 0; mt < 2; mt++)
#pragma unroll
                for (int nt = 0; nt < 8; nt++)
                    mma16(acc[mt][nt], a[mt], bf[nt]);
        }
        __syncthreads();
    }

    // Epilogue
#pragma unroll
    for (int mt = 0; mt < 2; mt++) {
#pragma unroll
        for (int i = 0; i < 2; i++) {
            const int m = m0 + wm + 16 * mt + g + 8 * i;
            if (m >= MTOT) continue;
            const int bq_ = m / NPAD, rq = m % NPAD;
#pragma unroll
            for (int nt = 0; nt < 8; nt++) {
                const int n = n0 + wn + nt * 8 + 2 * tig;
                float v0 = acc[mt][nt][2 * i + 0] + bias[n];
                float v1 = acc[mt][nt][2 * i + 1] + bias[n + 1];
                if (mode == 0) {          // q pre-scaled (log2-domain softmax)
                    const int hh = n >> 6, d = n & 63;
                    *(uint32_t*)&g_qh[(((size_t)bq_ * NH + hh) * NPAD + rq) * HD + d] =
                        f2h2(v0 * QSCALE, v1 * QSCALE);
                } else if (mode == 1) {   // k, pair-permuted within 64-half row
                    const int hh = n >> 6, d = n & 63;
                    const int dp = pperm(d >> 1) << 1;
                    *(uint32_t*)&g_kh[(((size_t)bq_ * NH + hh) * NPAD + rq) * HD + dp] =
                        f2h2(v0, v1);
                } else if (mode == 2) {   // v transposed [d][key], key pair-permuted
                    const int hh = n >> 6, d = n & 63;
                    const int rqp = (rq & ~63) | (pperm((rq & 63) >> 1) << 1) | (rq & 1);
                    g_vt[(((size_t)bq_ * NH + hh) * HD + d)     * VPITCH + rqp] = __float2half(v0);
                    g_vt[(((size_t)bq_ * NH + hh) * HD + d + 1) * VPITCH + rqp] = __float2half(v1);
                } else {                  // O-proj fp32 out
                    *reinterpret_cast<float2*>(&outp[(size_t)m * E_DIM + n]) =
                        make_float2(v0, v1);
                }
            }
        }
    }
}

// ---------------------------------------------------------------------------
// Flash attention, key-split warps: 256 threads = (4 q-slabs) x (2 key-halves).
// Each warp: 16 q-rows x 32 keys per tile. Fixed-reference log2 softmax makes
// O/lsum pure sums -> key-half warps accumulate independently, one cross-warp
// smem reduction at the very end. 2-stage cp.async for K/V/bias/mask.
// ---------------------------------------------------------------------------
__global__ __launch_bounds__(256, 2) void attn_f16(const float* __restrict__ bias)
{
    extern __shared__ __align__(16) uint32_t sma[];
    const uint32_t sb = smem_u32(sma);

    const int tid  = threadIdx.x;
    const int lane = tid & 31, warp = tid >> 5;
    const int g = lane >> 2, tig = lane & 3;
    const int qw = warp & 3, kw = warp >> 2;       // q-slab, key-half
    const int qt = blockIdx.x, h = blockIdx.y, b = blockIdx.z;
    const int bh = b * NH + h;
    const int qbase = qt * 64, slab = qw * 16;
    const int koff = kw * 32;                      // key offset within tile
    const int row0 = qbase + slab + g;
    const int row1 = row0 + 8;
    const bool ok0 = row0 < NPAD, ok1 = row1 < NPAD;
    const size_t biasEnd = (size_t)BB * NH * NPAD * NPAD * 4;

    // Q fragments (half2 direct from gmem; q layout unpermuted)
    uint32_t qf[4][4];
    {
        const uint32_t* q0 = (const uint32_t*)(g_qh + ((size_t)bh * NPAD + row0) * HD);
        const uint32_t* q1 = (const uint32_t*)(g_qh + ((size_t)bh * NPAD + row1) * HD);
#pragma unroll
        for (int kc = 0; kc < 4; kc++)
#pragma unroll
            for (int hf = 0; hf < 2; hf++) {
                const int u = 8 * kc + tig + 4 * hf;
                qf[kc][2 * hf + 0] = ok0 ? __ldg(&q0[u]) : 0u;
                qf[kc][2 * hf + 1] = ok1 ? __ldg(&q1[u]) : 0u;
            }
    }

    auto stage = [&](int buf, int kt) {
        const int kbase = kt * 64;
        const uint32_t base = sb + buf * STAGE_B;
        // K tile: 64 keys x 64 halves = 512 cpa16
#pragma unroll
        for (int it = 0; it < 2; it++) {
            const int idx = it * 256 + tid;
            const int key = idx >> 3, c = idx & 7;
            cpa16(base + key * (KV_STRIDE * 4) + c * 16,
                  g_kh + ((size_t)bh * NPAD + kbase + key) * HD + c * 8,
                  kbase + key < NPAD);
        }
        // V tile: 64 d x 64 keys = 512 cpa16
#pragma unroll
        for (int it = 0; it < 2; it++) {
            const int idx = it * 256 + tid;
            const int d = idx >> 3, c = idx & 7;
            cpa16(base + 10240 + d * (KV_STRIDE * 4) + c * 16,
                  g_vt + ((size_t)bh * HD + d) * VPITCH + kbase + c * 8,
                  true);
        }
        // bias tile: 64 rows x 17 chunks = 1088 cpa16
#pragma unroll
        for (int it = 0; it < 5; it++) {
            const int idx = it * 256 + tid;
            if (idx < 1088) {
                const int row = idx / 17, c = idx - row * 17;
                const int row_g = qbase + row;
                const size_t S = ((size_t)bh * NPAD + row_g) * NPAD + kbase;
                const size_t src = ((S * 4) & ~(size_t)15) + (size_t)c * 16;
                cpa16(base + 20480 + row * 272 + c * 16,
                      (const char*)bias + src,
                      (row_g < NPAD) && (src < biasEnd));
            }
        }
        // mask: 2 words per row
        if (tid < 64) {
            const int row_g = qbase + tid;
            cpa8(base + 37888 + tid * 8,
                 g_mbits + ((size_t)b * NPAD + row_g) * MWORDS + 2 * kt,
                 row_g < NPAD);
        }
    };

    float lsum[2] = {0.f, 0.f};
    float o[8][4];
#pragma unroll
    for (int nt = 0; nt < 8; nt++)
#pragma unroll
        for (int e = 0; e < 4; e++) o[nt][e] = 0.f;

    stage(0, 0); CP_COMMIT();

    for (int kt = 0; kt < 17; kt++) {
        const int kbase = kt * 64;
        if (kt < 16) { stage((kt + 1) & 1, kt + 1); CP_COMMIT(); }
        if (kt < 16) CP_WAIT1(); else CP_WAIT0();
        __syncthreads();

        const uint32_t* st = sma + (kt & 1) * STAGE_U32;
        const uint32_t* Ks = st;
        const uint32_t* Vt = st + 2560;
        const float*    Bs = (const float*)(st + 5120);
        const uint32_t* Mk = st + 9472;

        // S = Q K^T over this warp's 32-key half (4 n-tiles)
        float s[4][4];
#pragma unroll
        for (int nt = 0; nt < 4; nt++)
#pragma unroll
            for (int e = 0; e < 4; e++) s[nt][e] = -M2REF;
#pragma unroll
        for (int kc = 0; kc < 4; kc++) {
#pragma unroll
            for (int nt = 0; nt < 4; nt++) {
                const uint2 bb = *reinterpret_cast<const uint2*>(
                    &Ks[(koff + 8 * nt + g) * KV_STRIDE + kc * 8 + 2 * tig]);
                uint32_t bbr[2] = {bb.x, bb.y};
                mma16(s[nt], qf[kc], bbr);
            }
        }

        // bias (log2 domain) + mask (single word: kw selects it)
        const uint32_t w0 = Mk[(slab + g) * 2 + kw];
        const uint32_t w1 = Mk[(slab + g + 8) * 2 + kw];
        const int sh0 = (int)((((size_t)bh * NPAD + row0) * NPAD + kbase) & 3);
        const int sh1 = (int)((((size_t)bh * NPAD + row1) * NPAD + kbase) & 3);
        const float* br0 = Bs + (slab + g) * 68 + sh0 + koff;
        const float* br1 = Bs + (slab + g + 8) * 68 + sh1 + koff;
#pragma unroll
        for (int nt = 0; nt < 4; nt++) {
            const int j = 8 * nt + 2 * tig;        // local bit within key-half
            float v0 = __fmaf_rn(br0[j],     LOG2E, s[nt][0]);
            float v1 = __fmaf_rn(br0[j + 1], LOG2E, s[nt][1]);
            float v2 = __fmaf_rn(br1[j],     LOG2E, s[nt][2]);
            float v3 = __fmaf_rn(br1[j + 1], LOG2E, s[nt][3]);
            if (!((w0 >> j) & 1u))       v0 = -1e30f;
            if (!((w0 >> (j + 1)) & 1u)) v1 = -1e30f;
            if (!((w1 >> j) & 1u))       v2 = -1e30f;
            if (!((w1 >> (j + 1)) & 1u)) v3 = -1e30f;
            s[nt][0] = v0; s[nt][1] = v1; s[nt][2] = v2; s[nt][3] = v3;
        }

        // p = exp2(v); per-thread partial row sums
#pragma unroll
        for (int nt = 0; nt < 4; nt++) {
            float p0 = ex2(s[nt][0]);
            float p1 = ex2(s[nt][1]);
            float p2 = ex2(s[nt][2]);
            float p3 = ex2(s[nt][3]);
            s[nt][0] = p0; s[nt][1] = p1; s[nt][2] = p2; s[nt][3] = p3;
            lsum[0] += p0 + p1;
            lsum[1] += p2 + p3;
        }

        // O += P V over this warp's key half (2 k-chunks of 16)
#pragma unroll
        for (int kc2 = 0; kc2 < 2; kc2++) {
            uint32_t af[4];
            af[0] = f2h2(s[2 * kc2][0],     s[2 * kc2][1]);
            af[1] = f2h2(s[2 * kc2][2],     s[2 * kc2][3]);
            af[2] = f2h2(s[2 * kc2 + 1][0], s[2 * kc2 + 1][1]);
            af[3] = f2h2(s[2 * kc2 + 1][2], s[2 * kc2 + 1][3]);
            const int col = (kw * 2 + kc2) * 8 + 2 * tig;
#pragma unroll
            for (int nt = 0; nt < 8; nt++) {
                const uint2 bb = *reinterpret_cast<const uint2*>(
                    &Vt[(8 * nt + g) * KV_STRIDE + col]);
                uint32_t bbr[2] = {bb.x, bb.y};
                mma16(o[nt], af, bbr);
            }
        }
        __syncthreads();
    }

    // cross key-half reduction: kw=1 warps dump, kw=0 warps add (reuse stages)
    float* red = (float*)sma;
    const int slot = (qw * 32 + lane) * 36;
    if (kw == 1) {
#pragma unroll
        for (int nt = 0; nt < 8; nt++)
#pragma unroll
            for (int e = 0; e < 4; e++) red[slot + nt * 4 + e] = o[nt][e];
        red[slot + 32] = lsum[0];
        red[slot + 33] = lsum[1];
    }
    __syncthreads();
    if (kw == 0) {
#pragma unroll
        for (int nt = 0; nt < 8; nt++)
#pragma unroll
            for (int e = 0; e < 4; e++) o[nt][e] += red[slot + nt * 4 + e];
        lsum[0] += red[slot + 32];
        lsum[1] += red[slot + 33];

        // quad-reduce row sums once
        lsum[0] += __shfl_xor_sync(0xffffffffu, lsum[0], 1);
        lsum[0] += __shfl_xor_sync(0xffffffffu, lsum[0], 2);
        lsum[1] += __shfl_xor_sync(0xffffffffu, lsum[1], 1);
        lsum[1] += __shfl_xor_sync(0xffffffffu, lsum[1], 2);

        // epilogue: normalize + store half to g_atth, pair-permuted
        const float inv0 = (lsum[0] > 0.f) ? 1.f / lsum[0] : 0.f;
        const float inv1 = (lsum[1] > 0.f) ? 1.f / lsum[1] : 0.f;
        __half* ob = g_atth + (size_t)b * NPAD * E_DIM + h * HD;
#pragma unroll
        for (int nt = 0; nt < 8; nt++) {
            const int d = nt * 8 + 2 * tig;
            const int dp = pperm(d >> 1) << 1;
            if (ok0)
                *(uint32_t*)&ob[(size_t)row0 * E_DIM + dp] =
                    f2h2(o[nt][0] * inv0, o[nt][1] * inv0);
            if (ok1)
                *(uint32_t*)&ob[(size_t)row1 * E_DIM + dp] =
                    f2h2(o[nt][2] * inv1, o[nt][3] * inv1);
        }
    }
}

// ---------------------------------------------------------------------------
extern "C" void kernel_launch(void* const* d_in, const int* in_sizes, int n_in,
                              void* d_out, int out_size)
{
    const float* x  = (const float*)d_in[0];
    const float* ab = (const float*)d_in[1];
    const int*   pm = (const int*)d_in[2];
    const float* Wq = (const float*)d_in[3];
    const float* bq = (const float*)d_in[4];
    const float* Wk = (const float*)d_in[5];
    const float* bk = (const float*)d_in[6];
    const float* Wv = (const float*)d_in[7];
    const float* bv = (const float*)d_in[8];
    const float* Wo = (const float*)d_in[9];
    const float* bo = (const float*)d_in[10];
    float* out = (float*)d_out;

    cudaFuncSetAttribute(gemm_f16, cudaFuncAttributeMaxDynamicSharedMemorySize, GEMM_SMEM);
    cudaFuncSetAttribute(attn_f16, cudaFuncAttributeMaxDynamicSharedMemorySize, 2 * STAGE_B);

    prep_all<<<(PREP_TOTAL + 255) / 256, 256>>>(x, Wq, Wk, Wv, Wo, pm);

    gemm_f16<<<dim3(4, 65, 3), 256, GEMM_SMEM>>>(bq, bk, bv, nullptr, 1);

    attn_f16<<<dim3(17, NH, BB), 256, 2 * STAGE_B>>>(ab);

    gemm_f16<<<dim3(4, 65, 1), 256, GEMM_SMEM>>>(bo, nullptr, nullptr, out, 0);
}